// round 1
// baseline (speedup 1.0000x reference)
#include <cuda_runtime.h>
#include <cuda_bf16.h>
#include <math.h>

// Problem constants
#define BB 8
#define SS 1024
#define DD 512
#define HH 8
#define UU 64
#define FF 2048
#define LN_EPS 1e-3f

// ---------------- scratch (device globals; no allocation allowed) ----------
__device__ float g_q[HH * BB * SS * UU];            // [H,B,S,U]
__device__ float g_kT[HH * BB * UU * SS];           // [H,B,U,S]
__device__ float g_v[HH * BB * SS * DD];            // [H,B,S,D]
__device__ float g_scores[(size_t)HH * BB * SS * SS];  // [H,B,S,S]
__device__ float g_concat[BB * SS * (HH * DD)];     // [B,S,H*D]
__device__ float g_tmp[BB * SS * DD];               // mha out, then ff2 out
__device__ float g_h[BB * SS * DD];                 // LN1 output
__device__ float g_ff[BB * SS * FF];                // relu(ff1)

// ---------------- generic batched strided GEMM -----------------------------
// C[z][m,n] = alpha * sum_k A[z][m,k]*B[z][k,n] (+bias[n]) (+relu)
// per-batch offsets: z -> (z/HD, z%HD) with two strides per operand.
#define BM 128
#define BN 128
#define BK 16

__global__ __launch_bounds__(256)
void gemm_k(const float* __restrict__ A, const float* __restrict__ B,
            float* __restrict__ C, const float* __restrict__ bias,
            int M, int N, int K,
            int sAm, int sAk, int sBk, int sBn, int sCm, int sCn,
            int HD, int sA1, int sA2, int sB1, int sB2, int sC1, int sC2,
            float alpha, int relu)
{
    int z = blockIdx.z;
    A += (z / HD) * sA1 + (z % HD) * sA2;
    B += (z / HD) * sB1 + (z % HD) * sB2;
    C += (z / HD) * sC1 + (z % HD) * sC2;

    const int row0 = blockIdx.y * BM;
    const int col0 = blockIdx.x * BN;
    const int tid  = threadIdx.x;
    const int ty   = tid >> 4;   // 0..15
    const int tx   = tid & 15;   // 0..15

    __shared__ float As[BK][BM];
    __shared__ float Bs[BK][BN];

    float acc[8][8];
#pragma unroll
    for (int i = 0; i < 8; i++)
#pragma unroll
        for (int j = 0; j < 8; j++) acc[i][j] = 0.f;

    for (int k0 = 0; k0 < K; k0 += BK) {
        // load A tile (BM*BK = 2048 elems, 8 per thread)
#pragma unroll
        for (int l = 0; l < 8; l++) {
            int i = tid + l * 256;
            int mm = i & (BM - 1);
            int kk = i >> 7;
            int gm = row0 + mm, gk = k0 + kk;
            As[kk][mm] = (gm < M) ? A[gm * sAm + gk * sAk] : 0.f;
        }
        // load B tile
#pragma unroll
        for (int l = 0; l < 8; l++) {
            int i = tid + l * 256;
            int nn = i & (BN - 1);
            int kk = i >> 7;
            int gn = col0 + nn, gk = k0 + kk;
            Bs[kk][nn] = (gn < N) ? B[gk * sBk + gn * sBn] : 0.f;
        }
        __syncthreads();

#pragma unroll
        for (int kk = 0; kk < BK; kk++) {
            float a[8], b[8];
            *(float4*)(a)     = *(const float4*)&As[kk][ty * 8];
            *(float4*)(a + 4) = *(const float4*)&As[kk][ty * 8 + 4];
            *(float4*)(b)     = *(const float4*)&Bs[kk][tx * 8];
            *(float4*)(b + 4) = *(const float4*)&Bs[kk][tx * 8 + 4];
#pragma unroll
            for (int i = 0; i < 8; i++)
#pragma unroll
                for (int j = 0; j < 8; j++)
                    acc[i][j] = fmaf(a[i], b[j], acc[i][j]);
        }
        __syncthreads();
    }

    // epilogue
#pragma unroll
    for (int i = 0; i < 8; i++) {
        int r = row0 + ty * 8 + i;
        if (r >= M) continue;
#pragma unroll
        for (int j = 0; j < 8; j++) {
            int c = col0 + tx * 8 + j;
            if (c >= N) continue;
            float val = acc[i][j] * alpha;
            if (bias) val += bias[c];
            if (relu) val = fmaxf(val, 0.f);
            C[r * sCm + c * sCn] = val;
        }
    }
}

// ---------------- softmax over rows of length 1024 --------------------------
__global__ __launch_bounds__(256)
void softmax_k(float* __restrict__ S)
{
    float* p = S + (size_t)blockIdx.x * 1024;
    int t = threadIdx.x;
    float v[4];
    float m = -INFINITY;
#pragma unroll
    for (int i = 0; i < 4; i++) { v[i] = p[t + i * 256]; m = fmaxf(m, v[i]); }

    __shared__ float red[256];
    red[t] = m;
    __syncthreads();
    for (int s = 128; s > 0; s >>= 1) {
        if (t < s) red[t] = fmaxf(red[t], red[t + s]);
        __syncthreads();
    }
    m = red[0];
    __syncthreads();

    float sum = 0.f;
#pragma unroll
    for (int i = 0; i < 4; i++) { v[i] = __expf(v[i] - m); sum += v[i]; }
    red[t] = sum;
    __syncthreads();
    for (int s = 128; s > 0; s >>= 1) {
        if (t < s) red[t] += red[t + s];
        __syncthreads();
    }
    float inv = 1.f / red[0];
#pragma unroll
    for (int i = 0; i < 4; i++) p[t + i * 256] = v[i] * inv;
}

// ---------------- residual + layernorm (rows of 512) ------------------------
__global__ __launch_bounds__(256)
void ln_k(float* __restrict__ out, const float* __restrict__ a,
          const float* __restrict__ b, const float* __restrict__ gamma,
          const float* __restrict__ beta)
{
    size_t base = (size_t)blockIdx.x * DD;
    int t = threadIdx.x;
    float x0 = a[base + t]       + b[base + t];
    float x1 = a[base + t + 256] + b[base + t + 256];

    __shared__ float r1[256], r2[256];
    r1[t] = x0 + x1;
    r2[t] = x0 * x0 + x1 * x1;
    __syncthreads();
    for (int s = 128; s > 0; s >>= 1) {
        if (t < s) { r1[t] += r1[t + s]; r2[t] += r2[t + s]; }
        __syncthreads();
    }
    float mean = r1[0] * (1.f / DD);
    float var  = r2[0] * (1.f / DD) - mean * mean;
    float rstd = rsqrtf(var + LN_EPS);

    out[base + t]       = gamma[t]       * (x0 - mean) * rstd + beta[t];
    out[base + t + 256] = gamma[t + 256] * (x1 - mean) * rstd + beta[t + 256];
}

// ---------------- host side --------------------------------------------------
static void gemm(const float* A, const float* B, float* C, const float* bias,
                 int M, int N, int K, int nb, int HD,
                 int sAm, int sAk, int sBk, int sBn, int sCm, int sCn,
                 int sA1, int sA2, int sB1, int sB2, int sC1, int sC2,
                 float alpha, int relu)
{
    dim3 grid((N + BN - 1) / BN, (M + BM - 1) / BM, nb);
    gemm_k<<<grid, 256>>>(A, B, C, bias, M, N, K,
                          sAm, sAk, sBk, sBn, sCm, sCn,
                          HD, sA1, sA2, sB1, sB2, sC1, sC2, alpha, relu);
}

extern "C" void kernel_launch(void* const* d_in, const int* in_sizes, int n_in,
                              void* d_out, int out_size)
{
    const float* x      = (const float*)d_in[0];
    const float* qw     = (const float*)d_in[1];
    const float* kw     = (const float*)d_in[2];
    const float* vw     = (const float*)d_in[3];
    const float* lw     = (const float*)d_in[4];
    const float* gamma1 = (const float*)d_in[5];
    const float* beta1  = (const float*)d_in[6];
    const float* w1     = (const float*)d_in[7];
    const float* b1     = (const float*)d_in[8];
    const float* w2     = (const float*)d_in[9];
    const float* b2     = (const float*)d_in[10];
    const float* gamma2 = (const float*)d_in[11];
    const float* beta2  = (const float*)d_in[12];
    float* out = (float*)d_out;

    float *q, *kT, *v, *scores, *concat, *tmp, *h, *ff;
    cudaGetSymbolAddress((void**)&q,      g_q);
    cudaGetSymbolAddress((void**)&kT,     g_kT);
    cudaGetSymbolAddress((void**)&v,      g_v);
    cudaGetSymbolAddress((void**)&scores, g_scores);
    cudaGetSymbolAddress((void**)&concat, g_concat);
    cudaGetSymbolAddress((void**)&tmp,    g_tmp);
    cudaGetSymbolAddress((void**)&h,      g_h);
    cudaGetSymbolAddress((void**)&ff,     g_ff);

    const float scale = 1.0f / sqrtf((float)DD);

    // batches z = h*B + b, HD = B: z/HD = head, z%HD = batch
    // 1) Q projection: [S,U] per (h,b). A=x[b], B=qw[h], C=g_q[z]
    gemm(x, qw, q, nullptr, SS, UU, DD, HH * BB, BB,
         DD, 1,            /*A strides*/
         UU, 1,            /*B strides*/
         UU, 1,            /*C strides*/
         0, SS * DD,                       /* A: h->0, b->S*D */
         DD * UU, 0,                       /* B: h->D*U, b->0 */
         BB * SS * UU, SS * UU,            /* C: z*S*U */
         1.f, 0);

    // 2) K projection stored transposed: kT[h,b][u,s]
    gemm(x, kw, kT, nullptr, SS, UU, DD, HH * BB, BB,
         DD, 1,
         UU, 1,
         1, SS,                            /* C: row(s) stride 1, col(u) stride S */
         0, SS * DD,
         DD * UU, 0,
         BB * UU * SS, UU * SS,
         1.f, 0);

    // 3) V projection: [S,D] per (h,b)
    gemm(x, vw, v, nullptr, SS, DD, DD, HH * BB, BB,
         DD, 1,
         DD, 1,
         DD, 1,
         0, SS * DD,
         DD * DD, 0,
         BB * SS * DD, SS * DD,
         1.f, 0);

    // 4) scores = scale * Q @ K^T : [S,S] per (h,b)
    gemm(q, kT, scores, nullptr, SS, SS, UU, HH * BB, BB,
         UU, 1,
         SS, 1,                            /* B: k(u) stride S, n(t) stride 1 */
         SS, 1,
         BB * SS * UU, SS * UU,
         BB * UU * SS, UU * SS,
         BB * SS * SS, SS * SS,
         scale, 0);

    // 5) softmax rows
    softmax_k<<<HH * BB * SS, 256>>>(scores);

    // 6) attn = probs @ V, written straight into concat layout [B,S,H*D]
    gemm(scores, v, concat, nullptr, SS, DD, SS, HH * BB, BB,
         SS, 1,
         DD, 1,
         HH * DD, 1,                       /* C row stride = 4096 */
         BB * SS * SS, SS * SS,
         BB * SS * DD, SS * DD,
         DD, SS * HH * DD,                 /* C: h->512, b->S*4096 */
         1.f, 0);

    // 7) output projection: [B*S, 4096] @ [4096, 512]
    gemm(concat, lw, tmp, nullptr, BB * SS, DD, HH * DD, 1, 1,
         HH * DD, 1,
         DD, 1,
         DD, 1,
         0, 0, 0, 0, 0, 0,
         1.f, 0);

    // 8) h = LN(x + mha)
    ln_k<<<BB * SS, 256>>>(h, x, tmp, gamma1, beta1);

    // 9) ff = relu(h @ w1 + b1)
    gemm(h, w1, ff, b1, BB * SS, FF, DD, 1, 1,
         DD, 1,
         FF, 1,
         FF, 1,
         0, 0, 0, 0, 0, 0,
         1.f, 1);

    // 10) tmp = ff @ w2 + b2
    gemm(ff, w2, tmp, b2, BB * SS, DD, FF, 1, 1,
         FF, 1,
         DD, 1,
         DD, 1,
         0, 0, 0, 0, 0, 0,
         1.f, 0);

    // 11) out = LN(h + tmp)
    ln_k<<<BB * SS, 256>>>(out, h, tmp, gamma2, beta2);
}

// round 2
// speedup vs baseline: 4.1856x; 4.1856x over previous
#include <cuda_runtime.h>
#include <cuda_bf16.h>
#include <math.h>
#include <stdint.h>

// Problem constants
#define BB 8
#define SS 1024
#define DD 512
#define HH 8
#define UU 64
#define FF 2048
#define LN_EPS 1e-3f

// ---------------- scratch (device globals; no allocation allowed) ----------
__device__ float g_q[HH * BB * SS * UU];            // [H,B,S,U]
__device__ float g_kT[HH * BB * UU * SS];           // [H,B,U,S]
__device__ float g_v[HH * BB * SS * DD];            // [H,B,S,D]
__device__ float g_scores[(size_t)HH * BB * SS * SS];  // [H,B,S,S]
__device__ float g_concat[BB * SS * (HH * DD)];     // [B,S,H*D]
__device__ float g_tmp[BB * SS * DD];               // mha out, then ff2 out
__device__ float g_h[BB * SS * DD];                 // LN1 output
__device__ float g_ff[BB * SS * FF];                // relu(ff1)

// ---------------- tf32 tensor-core batched strided GEMM ---------------------
// C[z][m,n] = alpha * sum_k A[z][m,k]*B[z][k,n] (+bias[n]) (+relu)
// Assumes: A k-contiguous (stride 1 in k), B n-contiguous (stride 1 in n),
//          M % 128 == 0, K % 16 == 0.  N guarded.
#define BM 128
#define BN 128
#define BK 16
#define BKP 20   // padded k-stride (conflict-free fragment loads)

__device__ __forceinline__ uint32_t f2tf32(float x) {
    uint32_t y;
    asm("cvt.rna.tf32.f32 %0, %1;" : "=r"(y) : "f"(x));
    return y;
}

__device__ __forceinline__ void mma_tf32(float* c, const uint32_t* a, const uint32_t* b) {
    asm volatile(
        "mma.sync.aligned.m16n8k8.row.col.f32.tf32.tf32.f32 "
        "{%0,%1,%2,%3}, {%4,%5,%6,%7}, {%8,%9}, {%0,%1,%2,%3};\n"
        : "+f"(c[0]), "+f"(c[1]), "+f"(c[2]), "+f"(c[3])
        : "r"(a[0]), "r"(a[1]), "r"(a[2]), "r"(a[3]), "r"(b[0]), "r"(b[1]));
}

__global__ __launch_bounds__(128)
void gemm_tc(const float* __restrict__ A, const float* __restrict__ B,
             float* __restrict__ C, const float* __restrict__ bias,
             int M, int N, int K,
             int sAm, int sBk, int sCm, int sCn,
             int HD, int sA1, int sA2, int sB1, int sB2, int sC1, int sC2,
             float alpha, int relu)
{
    const int z = blockIdx.z;
    A += (size_t)(z / HD) * sA1 + (size_t)(z % HD) * sA2;
    B += (size_t)(z / HD) * sB1 + (size_t)(z % HD) * sB2;
    C += (size_t)(z / HD) * sC1 + (size_t)(z % HD) * sC2;

    const int row0 = blockIdx.y * BM;
    const int col0 = blockIdx.x * BN;
    const int tid  = threadIdx.x;
    const int w    = tid >> 5;
    const int lane = tid & 31;
    const int wm   = w & 1;          // 2 warps over M
    const int wn   = w >> 1;         // 2 warps over N
    const int r    = lane >> 2;      // 0..7
    const int cq   = lane & 3;       // 0..3

    __shared__ uint32_t As[2][BM][BKP];
    __shared__ uint32_t Bs[2][BN][BKP];

    float acc[4][8][4];
#pragma unroll
    for (int i = 0; i < 4; i++)
#pragma unroll
        for (int j = 0; j < 8; j++)
#pragma unroll
            for (int q = 0; q < 4; q++) acc[i][j][q] = 0.f;

    // staging registers
    float rA[16], rB[16];
    const int la = tid >> 4;   // 0..7  (A row group)
    const int lb = tid & 15;   // 0..15 (A k index)

    // ---- load tile k0 = 0 ----
#pragma unroll
    for (int l = 0; l < 16; l++)
        rA[l] = A[(size_t)(row0 + la + 8 * l) * sAm + lb];
    {
        const int gn = col0 + tid;
        const bool okn = (gn < N);
#pragma unroll
        for (int l = 0; l < 16; l++)
            rB[l] = okn ? B[(size_t)l * sBk + gn] : 0.f;
    }
#pragma unroll
    for (int l = 0; l < 16; l++) As[0][la + 8 * l][lb] = f2tf32(rA[l]);
#pragma unroll
    for (int l = 0; l < 16; l++) Bs[0][tid][l] = f2tf32(rB[l]);
    __syncthreads();

    int cur = 0;
    for (int k0 = 0; k0 < K; k0 += BK) {
        const bool nxt = (k0 + BK) < K;
        if (nxt) {
            const int kn = k0 + BK;
#pragma unroll
            for (int l = 0; l < 16; l++)
                rA[l] = A[(size_t)(row0 + la + 8 * l) * sAm + (kn + lb)];
            const int gn = col0 + tid;
            const bool okn = (gn < N);
#pragma unroll
            for (int l = 0; l < 16; l++)
                rB[l] = okn ? B[(size_t)(kn + l) * sBk + gn] : 0.f;
        }

        // ---- compute from smem buffer `cur` ----
#pragma unroll
        for (int k8 = 0; k8 < BK; k8 += 8) {
            uint32_t af[4][4];
            uint32_t bf[8][2];
#pragma unroll
            for (int mt = 0; mt < 4; mt++) {
                const int row = wm * 64 + mt * 16 + r;
                af[mt][0] = As[cur][row][k8 + cq];
                af[mt][1] = As[cur][row + 8][k8 + cq];
                af[mt][2] = As[cur][row][k8 + cq + 4];
                af[mt][3] = As[cur][row + 8][k8 + cq + 4];
            }
#pragma unroll
            for (int nt = 0; nt < 8; nt++) {
                const int col = wn * 64 + nt * 8 + r;
                bf[nt][0] = Bs[cur][col][k8 + cq];
                bf[nt][1] = Bs[cur][col][k8 + cq + 4];
            }
#pragma unroll
            for (int mt = 0; mt < 4; mt++)
#pragma unroll
                for (int nt = 0; nt < 8; nt++)
                    mma_tf32(acc[mt][nt], af[mt], bf[nt]);
        }

        if (nxt) {
            const int nb = cur ^ 1;
#pragma unroll
            for (int l = 0; l < 16; l++) As[nb][la + 8 * l][lb] = f2tf32(rA[l]);
#pragma unroll
            for (int l = 0; l < 16; l++) Bs[nb][tid][l] = f2tf32(rB[l]);
            cur = nb;
            __syncthreads();
        }
    }

    // ---- epilogue ----
#pragma unroll
    for (int mt = 0; mt < 4; mt++) {
        const int rr0 = row0 + wm * 64 + mt * 16 + r;
        const int rr1 = rr0 + 8;
#pragma unroll
        for (int nt = 0; nt < 8; nt++) {
            const int cc0 = col0 + wn * 64 + nt * 8 + 2 * cq;
            const int cc1 = cc0 + 1;
            if (cc0 < N) {
                float v0 = acc[mt][nt][0] * alpha;
                float v2 = acc[mt][nt][2] * alpha;
                if (bias) { v0 += bias[cc0]; v2 += bias[cc0]; }
                if (relu) { v0 = fmaxf(v0, 0.f); v2 = fmaxf(v2, 0.f); }
                C[(size_t)rr0 * sCm + (size_t)cc0 * sCn] = v0;
                C[(size_t)rr1 * sCm + (size_t)cc0 * sCn] = v2;
            }
            if (cc1 < N) {
                float v1 = acc[mt][nt][1] * alpha;
                float v3 = acc[mt][nt][3] * alpha;
                if (bias) { v1 += bias[cc1]; v3 += bias[cc1]; }
                if (relu) { v1 = fmaxf(v1, 0.f); v3 = fmaxf(v3, 0.f); }
                C[(size_t)rr0 * sCm + (size_t)cc1 * sCn] = v1;
                C[(size_t)rr1 * sCm + (size_t)cc1 * sCn] = v3;
            }
        }
    }
}

// ---------------- softmax over rows of length 1024 --------------------------
__global__ __launch_bounds__(256)
void softmax_k(float* __restrict__ S)
{
    float* p = S + (size_t)blockIdx.x * 1024;
    int t = threadIdx.x;
    float v[4];
    float m = -INFINITY;
#pragma unroll
    for (int i = 0; i < 4; i++) { v[i] = p[t + i * 256]; m = fmaxf(m, v[i]); }

    __shared__ float red[256];
    red[t] = m;
    __syncthreads();
    for (int s = 128; s > 0; s >>= 1) {
        if (t < s) red[t] = fmaxf(red[t], red[t + s]);
        __syncthreads();
    }
    m = red[0];
    __syncthreads();

    float sum = 0.f;
#pragma unroll
    for (int i = 0; i < 4; i++) { v[i] = __expf(v[i] - m); sum += v[i]; }
    red[t] = sum;
    __syncthreads();
    for (int s = 128; s > 0; s >>= 1) {
        if (t < s) red[t] += red[t + s];
        __syncthreads();
    }
    float inv = 1.f / red[0];
#pragma unroll
    for (int i = 0; i < 4; i++) p[t + i * 256] = v[i] * inv;
}

// ---------------- residual + layernorm (rows of 512) ------------------------
__global__ __launch_bounds__(256)
void ln_k(float* __restrict__ out, const float* __restrict__ a,
          const float* __restrict__ b, const float* __restrict__ gamma,
          const float* __restrict__ beta)
{
    size_t base = (size_t)blockIdx.x * DD;
    int t = threadIdx.x;
    float x0 = a[base + t]       + b[base + t];
    float x1 = a[base + t + 256] + b[base + t + 256];

    __shared__ float r1[256], r2[256];
    r1[t] = x0 + x1;
    r2[t] = x0 * x0 + x1 * x1;
    __syncthreads();
    for (int s = 128; s > 0; s >>= 1) {
        if (t < s) { r1[t] += r1[t + s]; r2[t] += r2[t + s]; }
        __syncthreads();
    }
    float mean = r1[0] * (1.f / DD);
    float var  = r2[0] * (1.f / DD) - mean * mean;
    float rstd = rsqrtf(var + LN_EPS);

    out[base + t]       = gamma[t]       * (x0 - mean) * rstd + beta[t];
    out[base + t + 256] = gamma[t + 256] * (x1 - mean) * rstd + beta[t + 256];
}

// ---------------- host side --------------------------------------------------
static void gemm(const float* A, const float* B, float* C, const float* bias,
                 int M, int N, int K, int nb, int HD,
                 int sAm, int sBk, int sCm, int sCn,
                 int sA1, int sA2, int sB1, int sB2, int sC1, int sC2,
                 float alpha, int relu)
{
    dim3 grid((N + BN - 1) / BN, (M + BM - 1) / BM, nb);
    gemm_tc<<<grid, 128>>>(A, B, C, bias, M, N, K,
                           sAm, sBk, sCm, sCn,
                           HD, sA1, sA2, sB1, sB2, sC1, sC2, alpha, relu);
}

extern "C" void kernel_launch(void* const* d_in, const int* in_sizes, int n_in,
                              void* d_out, int out_size)
{
    const float* x      = (const float*)d_in[0];
    const float* qw     = (const float*)d_in[1];
    const float* kw     = (const float*)d_in[2];
    const float* vw     = (const float*)d_in[3];
    const float* lw     = (const float*)d_in[4];
    const float* gamma1 = (const float*)d_in[5];
    const float* beta1  = (const float*)d_in[6];
    const float* w1     = (const float*)d_in[7];
    const float* b1     = (const float*)d_in[8];
    const float* w2     = (const float*)d_in[9];
    const float* b2     = (const float*)d_in[10];
    const float* gamma2 = (const float*)d_in[11];
    const float* beta2  = (const float*)d_in[12];
    float* out = (float*)d_out;

    float *q, *kT, *v, *scores, *concat, *tmp, *h, *ff;
    cudaGetSymbolAddress((void**)&q,      g_q);
    cudaGetSymbolAddress((void**)&kT,     g_kT);
    cudaGetSymbolAddress((void**)&v,      g_v);
    cudaGetSymbolAddress((void**)&scores, g_scores);
    cudaGetSymbolAddress((void**)&concat, g_concat);
    cudaGetSymbolAddress((void**)&tmp,    g_tmp);
    cudaGetSymbolAddress((void**)&h,      g_h);
    cudaGetSymbolAddress((void**)&ff,     g_ff);

    const float scale = 1.0f / sqrtf((float)DD);

    // batches z = h*B + b, HD = B: z/HD = head, z%HD = batch
    // 1) Q projection: [S,U] per (h,b)
    gemm(x, qw, q, nullptr, SS, UU, DD, HH * BB, BB,
         DD, UU, UU, 1,
         0, SS * DD,
         DD * UU, 0,
         BB * SS * UU, SS * UU,
         1.f, 0);

    // 2) K projection stored transposed: kT[h,b][u,s]
    gemm(x, kw, kT, nullptr, SS, UU, DD, HH * BB, BB,
         DD, UU, 1, SS,
         0, SS * DD,
         DD * UU, 0,
         BB * UU * SS, UU * SS,
         1.f, 0);

    // 3) V projection: [S,D] per (h,b)
    gemm(x, vw, v, nullptr, SS, DD, DD, HH * BB, BB,
         DD, DD, DD, 1,
         0, SS * DD,
         DD * DD, 0,
         BB * SS * DD, SS * DD,
         1.f, 0);

    // 4) scores = scale * Q @ K^T : [S,S] per (h,b)
    gemm(q, kT, scores, nullptr, SS, SS, UU, HH * BB, BB,
         UU, SS, SS, 1,
         BB * SS * UU, SS * UU,
         BB * UU * SS, UU * SS,
         BB * SS * SS, SS * SS,
         scale, 0);

    // 5) softmax rows
    softmax_k<<<HH * BB * SS, 256>>>(scores);

    // 6) attn = probs @ V, written straight into concat layout [B,S,H*D]
    gemm(scores, v, concat, nullptr, SS, DD, SS, HH * BB, BB,
         SS, DD, HH * DD, 1,
         BB * SS * SS, SS * SS,
         BB * SS * DD, SS * DD,
         DD, SS * HH * DD,
         1.f, 0);

    // 7) output projection: [B*S, 4096] @ [4096, 512]
    gemm(concat, lw, tmp, nullptr, BB * SS, DD, HH * DD, 1, 1,
         HH * DD, DD, DD, 1,
         0, 0, 0, 0, 0, 0,
         1.f, 0);

    // 8) h = LN(x + mha)
    ln_k<<<BB * SS, 256>>>(h, x, tmp, gamma1, beta1);

    // 9) ff = relu(h @ w1 + b1)
    gemm(h, w1, ff, b1, BB * SS, FF, DD, 1, 1,
         DD, FF, FF, 1,
         0, 0, 0, 0, 0, 0,
         1.f, 1);

    // 10) tmp = ff @ w2 + b2
    gemm(ff, w2, tmp, b2, BB * SS, DD, FF, 1, 1,
         FF, DD, DD, 1,
         0, 0, 0, 0, 0, 0,
         1.f, 0);

    // 11) out = LN(h + tmp)
    ln_k<<<BB * SS, 256>>>(out, h, tmp, gamma2, beta2);
}